// round 5
// baseline (speedup 1.0000x reference)
#include <cuda_runtime.h>
#include <cuda_bf16.h>
#include <cstdint>
#include <cstddef>

// Problem constants
#define Bb   2
#define Ss   2048
#define Hh   2048
#define NHh  16
#define HDd  128
#define Pp   2048
#define Mm   (Bb * Ss)          // 4096 rows
#define H2   (Hh / 2)           // 1024
#define QKW  (2 * Pp)           // 4096 (qk row width)
#define EPSc 1e-6f

// ---------------- scratch (static device globals; no allocation) ----------------
__device__ float g_v[(size_t)Mm * Pp];
__device__ float g_xprev[(size_t)Mm * Hh];
__device__ float g_y1[(size_t)Mm * H2];
__device__ float g_y1prev[(size_t)Mm * H2];
__device__ float g_lfout[(size_t)Mm * Hh];
__device__ float g_qk[(size_t)Mm * QKW];
__device__ float g_attn[(size_t)Mm * Pp];
__device__ float g_w1a[(size_t)H2 * Hh];
__device__ float g_w1b[(size_t)H2 * Hh];
__device__ float g_w2a[(size_t)Hh * H2];
__device__ float g_w2b[(size_t)Hh * H2];

// ---------------- helpers ----------------
__device__ __forceinline__ uint32_t f2tf(float x) {
    uint32_t r;
    asm("cvt.rna.tf32.f32 %0, %1;" : "=r"(r) : "f"(x));
    return r;
}

__device__ __forceinline__ void mma_tf32(float* d, const uint32_t* a, const uint32_t* b) {
    asm volatile(
        "mma.sync.aligned.m16n8k8.row.col.f32.tf32.tf32.f32 "
        "{%0,%1,%2,%3},{%4,%5,%6,%7},{%8,%9},{%0,%1,%2,%3};"
        : "+f"(d[0]), "+f"(d[1]), "+f"(d[2]), "+f"(d[3])
        : "r"(a[0]), "r"(a[1]), "r"(a[2]), "r"(a[3]), "r"(b[0]), "r"(b[1]));
}

__device__ __forceinline__ void cp16(void* smem, const void* g) {
    uint32_t s = (uint32_t)__cvta_generic_to_shared(smem);
    asm volatile("cp.async.ca.shared.global [%0], [%1], 16;" :: "r"(s), "l"(g));
}

// ---------------- deinterleave conv weights ----------------
__global__ void deint_kernel(const float* __restrict__ in, float* __restrict__ a,
                             float* __restrict__ b, int n)
{
    int i = blockIdx.x * 256 + threadIdx.x;
    if (i < n) {
        a[i] = in[2 * i];
        b[i] = in[2 * i + 1];
    }
}

// ---------------- shift rows by one seq step ----------------
__global__ void shift_kernel(const float* __restrict__ x, const float* __restrict__ cache,
                             float* __restrict__ out, int width)
{
    int m = blockIdx.x;
    int s = m % Ss;
    int b = m / Ss;
    const float* src = (s == 0) ? (cache + (size_t)b * width)
                                : (x + (size_t)(m - 1) * width);
    float* dst = out + (size_t)m * width;
    for (int i = threadIdx.x; i < width; i += 256) dst[i] = src[i];
}

// ---------------- TF32 tensor-core GEMM (NT): C[M,N] = A[M,K] * W[N,K]^T (+bias)(+C) ----------------
// 128x128 block tile, BK=16, 256 threads = 8 warps (2x4), warp tile 64x32 via m16n8k8.
// All dims % 128 == 0, K % 16 == 0.
#define BMg 128
#define BNg 128
#define BKg 16
#define PADg 20   // floats per smem row (keeps 16B align, conflict-free frags)

__global__ __launch_bounds__(256) void gemm_tf32_kernel(
    const float* __restrict__ A, const float* __restrict__ W, float* __restrict__ C,
    int N, int K, const float* __restrict__ bias, int accFlag)
{
    __shared__ float As[2][BMg * PADg];
    __shared__ float Bs[2][BNg * PADg];

    const int tid = threadIdx.x;
    const int lane = tid & 31;
    const int warp = tid >> 5;
    const int wm = warp >> 2;          // 0..1
    const int wn = warp & 3;           // 0..3
    const int bm = blockIdx.y * BMg;
    const int bn = blockIdx.x * BNg;
    const int mBase = wm * 64;
    const int nBase = wn * 32;

    float acc[4][4][4];
#pragma unroll
    for (int mi = 0; mi < 4; mi++)
#pragma unroll
        for (int ni = 0; ni < 4; ni++)
#pragma unroll
            for (int e = 0; e < 4; e++) acc[mi][ni][e] = 0.f;

    const int nk = K / BKg;

    // chunk c in [0,512): row = c>>2, col floats = (c&3)*4 ; thread does c=tid, tid+256
    auto load_tiles = [&](int buf, int k0) {
#pragma unroll
        for (int c = tid; c < 512; c += 256) {
            int row = c >> 2;
            int colf = (c & 3) << 2;
            cp16(&As[buf][row * PADg + colf], A + (size_t)(bm + row) * K + k0 + colf);
            cp16(&Bs[buf][row * PADg + colf], W + (size_t)(bn + row) * K + k0 + colf);
        }
        asm volatile("cp.async.commit_group;");
    };

    load_tiles(0, 0);

    const int row4 = lane >> 2;   // 0..7
    const int col4 = lane & 3;    // 0..3

    for (int kt = 0; kt < nk; kt++) {
        int buf = kt & 1;
        if (kt + 1 < nk) {
            load_tiles(buf ^ 1, (kt + 1) * BKg);
            asm volatile("cp.async.wait_group 1;");
        } else {
            asm volatile("cp.async.wait_group 0;");
        }
        __syncthreads();

        const float* as = &As[buf][0];
        const float* bs = &Bs[buf][0];
#pragma unroll
        for (int kk = 0; kk < BKg; kk += 8) {
            uint32_t af[4][4], bf[4][2];
#pragma unroll
            for (int mi = 0; mi < 4; mi++) {
                int m0 = mBase + mi * 16;
                af[mi][0] = f2tf(as[(m0 + row4) * PADg + kk + col4]);
                af[mi][1] = f2tf(as[(m0 + row4 + 8) * PADg + kk + col4]);
                af[mi][2] = f2tf(as[(m0 + row4) * PADg + kk + col4 + 4]);
                af[mi][3] = f2tf(as[(m0 + row4 + 8) * PADg + kk + col4 + 4]);
            }
#pragma unroll
            for (int ni = 0; ni < 4; ni++) {
                int n0 = nBase + ni * 8;
                bf[ni][0] = f2tf(bs[(n0 + row4) * PADg + kk + col4]);
                bf[ni][1] = f2tf(bs[(n0 + row4) * PADg + kk + col4 + 4]);
            }
#pragma unroll
            for (int mi = 0; mi < 4; mi++)
#pragma unroll
                for (int ni = 0; ni < 4; ni++)
                    mma_tf32(acc[mi][ni], af[mi], bf[ni]);
        }
        __syncthreads();
    }

    // epilogue: c0,c1 at (row4, 2*col4+{0,1}); c2,c3 at (row4+8, same)
#pragma unroll
    for (int mi = 0; mi < 4; mi++) {
        int r0 = bm + mBase + mi * 16 + row4;
#pragma unroll
        for (int ni = 0; ni < 4; ni++) {
            int cb = bn + nBase + ni * 8 + 2 * col4;
            float2 b2 = make_float2(0.f, 0.f);
            if (bias) { b2.x = bias[cb]; b2.y = bias[cb + 1]; }

            float* p0 = C + (size_t)r0 * N + cb;
            float* p1 = C + (size_t)(r0 + 8) * N + cb;
            float2 v0 = make_float2(acc[mi][ni][0] + b2.x, acc[mi][ni][1] + b2.y);
            float2 v1 = make_float2(acc[mi][ni][2] + b2.x, acc[mi][ni][3] + b2.y);
            if (accFlag) {
                float2 o0 = *(float2*)p0, o1 = *(float2*)p1;
                v0.x += o0.x; v0.y += o0.y;
                v1.x += o1.x; v1.y += o1.y;
            }
            *(float2*)p0 = v0;
            *(float2*)p1 = v1;
        }
    }
}

// ---------------- residual add + RMSNorm (in-place into y2 buffer) ----------------
__global__ __launch_bounds__(256) void rmsnorm_kernel(
    float* __restrict__ y2, const float* __restrict__ x, const float* __restrict__ w)
{
    int m = blockIdx.x;
    float* yrow = y2 + (size_t)m * Hh;
    const float* xrow = x + (size_t)m * Hh;

    float ss = 0.f;
    for (int i = threadIdx.x; i < Hh; i += 256) {
        float t = yrow[i] + xrow[i];
        ss += t * t;
    }
#pragma unroll
    for (int off = 16; off > 0; off >>= 1)
        ss += __shfl_xor_sync(0xffffffffu, ss, off);

    __shared__ float red[9];
    int lane = threadIdx.x & 31, wid = threadIdx.x >> 5;
    if (lane == 0) red[wid] = ss;
    __syncthreads();
    if (threadIdx.x == 0) {
        float tot = 0.f;
        for (int i = 0; i < 8; i++) tot += red[i];
        red[8] = rsqrtf(tot / (float)Hh + EPSc);
    }
    __syncthreads();
    float inv = red[8];
    for (int i = threadIdx.x; i < Hh; i += 256) {
        float t = yrow[i] + xrow[i];
        yrow[i] = t * w[i] * inv;
    }
}

// ---------------- RoPE in place on qk buffer ----------------
__global__ __launch_bounds__(128) void rope_kernel(
    float* __restrict__ qkbuf, const float* __restrict__ freqs,
    const int* __restrict__ positions)
{
    int mh = blockIdx.x;
    int m = mh / NHh, h = mh % NHh;
    int pos = positions[m];
    int t = threadIdx.x;
    int isK = t >> 6;
    int d = t & 63;

    size_t base = (size_t)m * QKW + (size_t)h * 256 + (size_t)isK * 128;
    float f1 = freqs[(size_t)pos * HDd + d];
    float f2 = freqs[(size_t)pos * HDd + d + 64];
    float c1 = cosf(f1), s1 = sinf(f1);
    float c2 = cosf(f2), s2 = sinf(f2);
    float x1 = qkbuf[base + d];
    float x2 = qkbuf[base + d + 64];
    qkbuf[base + d]      = x1 * c1 - x2 * s1;
    qkbuf[base + d + 64] = x2 * c2 + x1 * s2;
}

// ---------------- causal flash attention ----------------
#define TQ 64
#define TK 32
__global__ __launch_bounds__(256) void flash_kernel(
    const float* __restrict__ qkbuf, const float* __restrict__ vbuf,
    float* __restrict__ attn)
{
    int qt = blockIdx.x;
    int h  = blockIdx.y;
    int b  = blockIdx.z;
    int q0 = qt * TQ;
    int tid = threadIdx.x;
    int g = tid >> 2;
    int part = tid & 3;

    __shared__ float Ks[TK][HDd];
    __shared__ float Vs[TK][HDd];

    int qi = q0 + g;
    size_t qbase = (size_t)(b * Ss + qi) * QKW + (size_t)h * 256;
    const float scale = 0.08838834764831845f;

    float qr[32], o[32];
#pragma unroll
    for (int i = 0; i < 32; i++) {
        qr[i] = qkbuf[qbase + i * 4 + part] * scale;
        o[i] = 0.f;
    }
    float mval = -1e30f, lval = 0.f;

    int kend = q0 + TQ;
    for (int j0 = 0; j0 < kend; j0 += TK) {
        __syncthreads();
        for (int t = tid; t < TK * HDd / 4; t += 256) {
            int row = t >> 5;
            int c4 = (t & 31) << 2;
            size_t kb = (size_t)(b * Ss + j0 + row) * QKW + (size_t)h * 256 + 128 + c4;
            size_t vb = (size_t)(b * Ss + j0 + row) * Pp + (size_t)h * HDd + c4;
            *(float4*)&Ks[row][c4] = *(const float4*)(qkbuf + kb);
            *(float4*)&Vs[row][c4] = *(const float4*)(vbuf + vb);
        }
        __syncthreads();

#pragma unroll 1
        for (int j = 0; j < TK; j++) {
            int kpos = j0 + j;
            float s = 0.f;
#pragma unroll
            for (int i = 0; i < 32; i++) s = fmaf(qr[i], Ks[j][i * 4 + part], s);
            s += __shfl_xor_sync(0xffffffffu, s, 1);
            s += __shfl_xor_sync(0xffffffffu, s, 2);
            if (kpos > qi) s = -1e30f;

            float mnew = fmaxf(mval, s);
            float alpha = __expf(mval - mnew);
            float p = __expf(s - mnew);
            lval = lval * alpha + p;
            mval = mnew;
#pragma unroll
            for (int i = 0; i < 32; i++)
                o[i] = fmaf(o[i], alpha, p * Vs[j][i * 4 + part]);
        }
    }

    float inv = 1.f / lval;
    size_t ob = (size_t)(b * Ss + qi) * Pp + (size_t)h * HDd;
#pragma unroll
    for (int i = 0; i < 32; i++) attn[ob + i * 4 + part] = o[i] * inv;
}

// ---------------- tail outputs ----------------
__global__ void tails_kernel(const float* __restrict__ hs, const float* __restrict__ y1,
                             float* __restrict__ out)
{
    int i = blockIdx.x * 256 + threadIdx.x;
    size_t off1 = (size_t)Mm * Hh;
    size_t off2 = off1 + (size_t)Bb * Hh;
    if (i < Bb * Hh) {
        int b = i / Hh, hh = i % Hh;
        out[off1 + i] = hs[((size_t)b * Ss + (Ss - 1)) * Hh + hh];
    }
    if (i < Bb * H2) {
        int b = i / H2, oo = i % H2;
        out[off2 + i] = y1[((size_t)b * Ss + (Ss - 1)) * H2 + oo];
    }
}

// ---------------- launch ----------------
extern "C" void kernel_launch(void* const* d_in, const int* in_sizes, int n_in,
                              void* d_out, int out_size)
{
    (void)in_sizes; (void)n_in; (void)out_size;
    const float* hs      = (const float*)d_in[0];
    const float* freqs   = (const float*)d_in[1];
    const int*   pos     = (const int*)  d_in[2];
    const float* Wqk     = (const float*)d_in[3];
    const float* Wv      = (const float*)d_in[4];
    const float* Wo      = (const float*)d_in[5];
    const float* conv1_w = (const float*)d_in[6];
    const float* conv1_b = (const float*)d_in[7];
    const float* conv2_w = (const float*)d_in[8];
    const float* conv2_b = (const float*)d_in[9];
    const float* ln_w    = (const float*)d_in[10];
    const float* lf1c    = (const float*)d_in[11];
    const float* lf2c    = (const float*)d_in[12];
    float* out = (float*)d_out;

    float *v, *xprev, *y1, *y1prev, *lfout, *qk, *attn;
    float *w1a, *w1b, *w2a, *w2b;
    cudaGetSymbolAddress((void**)&v,      g_v);
    cudaGetSymbolAddress((void**)&xprev,  g_xprev);
    cudaGetSymbolAddress((void**)&y1,     g_y1);
    cudaGetSymbolAddress((void**)&y1prev, g_y1prev);
    cudaGetSymbolAddress((void**)&lfout,  g_lfout);
    cudaGetSymbolAddress((void**)&qk,     g_qk);
    cudaGetSymbolAddress((void**)&attn,   g_attn);
    cudaGetSymbolAddress((void**)&w1a,    g_w1a);
    cudaGetSymbolAddress((void**)&w1b,    g_w1b);
    cudaGetSymbolAddress((void**)&w2a,    g_w2a);
    cudaGetSymbolAddress((void**)&w2b,    g_w2b);

    // 1) deinterleave conv weights
    {
        int n1 = H2 * Hh;
        deint_kernel<<<(n1 + 255) / 256, 256>>>(conv1_w, w1a, w1b, n1);
        int n2 = Hh * H2;
        deint_kernel<<<(n2 + 255) / 256, 256>>>(conv2_w, w2a, w2b, n2);
    }

    // 2) shifted hidden
    shift_kernel<<<Mm, 256>>>(hs, lf1c, xprev, Hh);

    // 3) v = hs @ Wv^T
    gemm_tf32_kernel<<<dim3(Pp / BNg, Mm / BMg), 256>>>(hs, Wv, v, Pp, Hh, nullptr, 0);

    // 4) y1 = xprev @ w1a^T + hs @ w1b^T + b1
    gemm_tf32_kernel<<<dim3(H2 / BNg, Mm / BMg), 256>>>(xprev, w1a, y1, H2, Hh, nullptr, 0);
    gemm_tf32_kernel<<<dim3(H2 / BNg, Mm / BMg), 256>>>(hs,    w1b, y1, H2, Hh, conv1_b, 1);

    // 5) shifted y1
    shift_kernel<<<Mm, 256>>>(y1, lf2c, y1prev, H2);

    // 6) y2 = y1prev @ w2a^T + y1 @ w2b^T + b2
    gemm_tf32_kernel<<<dim3(Hh / BNg, Mm / BMg), 256>>>(y1prev, w2a, lfout, Hh, H2, nullptr, 0);
    gemm_tf32_kernel<<<dim3(Hh / BNg, Mm / BMg), 256>>>(y1,     w2b, lfout, Hh, H2, conv2_b, 1);

    // 7) lf_out = rmsnorm(y2 + hs) * ln_w
    rmsnorm_kernel<<<Mm, 256>>>(lfout, hs, ln_w);

    // 8) qk = lf_out @ Wqk^T
    gemm_tf32_kernel<<<dim3(QKW / BNg, Mm / BMg), 256>>>(lfout, Wqk, qk, QKW, Hh, nullptr, 0);

    // 9) RoPE in place
    rope_kernel<<<Mm * NHh, 128>>>(qk, freqs, pos);

    // 10) causal flash attention
    flash_kernel<<<dim3(Ss / TQ, NHh, Bb), 256>>>(qk, v, attn);

    // 11) output = attn @ Wo^T
    gemm_tf32_kernel<<<dim3(Hh / BNg, Mm / BMg), 256>>>(attn, Wo, out, Hh, Pp, nullptr, 0);

    // 12) tails
    tails_kernel<<<(Bb * Hh + 255) / 256, 256>>>(hs, y1, out);
}

// round 6
// speedup vs baseline: 1.6787x; 1.6787x over previous
#include <cuda_runtime.h>
#include <cuda_bf16.h>
#include <cstdint>
#include <cstddef>

// Problem constants
#define Bb   2
#define Ss   2048
#define Hh   2048
#define NHh  16
#define HDd  128
#define Pp   2048
#define Mm   (Bb * Ss)          // 4096 rows
#define H2   (Hh / 2)           // 1024
#define QKW  (2 * Pp)           // 4096 (qk row width)
#define EPSc 1e-6f

// ---------------- scratch (static device globals; no allocation) ----------------
__device__ float g_v[(size_t)Mm * Pp];
__device__ float g_xprev[(size_t)Mm * Hh];
__device__ float g_y1[(size_t)Mm * H2];
__device__ float g_y1prev[(size_t)Mm * H2];
__device__ float g_lfout[(size_t)Mm * Hh];
__device__ float g_qk[(size_t)Mm * QKW];
__device__ float g_attn[(size_t)Mm * Pp];
__device__ float g_w1a[(size_t)H2 * Hh];
__device__ float g_w1b[(size_t)H2 * Hh];
__device__ float g_w2a[(size_t)Hh * H2];
__device__ float g_w2b[(size_t)Hh * H2];

// ---------------- helpers ----------------
__device__ __forceinline__ uint32_t f2tf(float x) {
    uint32_t r;
    asm("cvt.rna.tf32.f32 %0, %1;" : "=r"(r) : "f"(x));
    return r;
}

__device__ __forceinline__ void mma_tf32(float* d, const uint32_t* a, const uint32_t* b) {
    asm volatile(
        "mma.sync.aligned.m16n8k8.row.col.f32.tf32.tf32.f32 "
        "{%0,%1,%2,%3},{%4,%5,%6,%7},{%8,%9},{%0,%1,%2,%3};"
        : "+f"(d[0]), "+f"(d[1]), "+f"(d[2]), "+f"(d[3])
        : "r"(a[0]), "r"(a[1]), "r"(a[2]), "r"(a[3]), "r"(b[0]), "r"(b[1]));
}

__device__ __forceinline__ void sts_cvt(uint32_t* p, float4 v) {
    uint4 u;
    u.x = f2tf(v.x); u.y = f2tf(v.y); u.z = f2tf(v.z); u.w = f2tf(v.w);
    *(uint4*)p = u;
}

// ---------------- deinterleave conv weights ----------------
__global__ void deint_kernel(const float* __restrict__ in, float* __restrict__ a,
                             float* __restrict__ b, int n)
{
    int i = blockIdx.x * 256 + threadIdx.x;
    if (i < n) {
        a[i] = in[2 * i];
        b[i] = in[2 * i + 1];
    }
}

// ---------------- shift rows by one seq step ----------------
__global__ void shift_kernel(const float* __restrict__ x, const float* __restrict__ cache,
                             float* __restrict__ out, int width)
{
    int m = blockIdx.x;
    int s = m % Ss;
    int b = m / Ss;
    const float* src = (s == 0) ? (cache + (size_t)b * width)
                                : (x + (size_t)(m - 1) * width);
    float* dst = out + (size_t)m * width;
    for (int i = threadIdx.x; i < width; i += 256) dst[i] = src[i];
}

// ---------------- TF32 tensor-core GEMM (NT), convert-on-stage, optional dual-K ----------------
// C[M,N] = A[M,K] * W[N,K]^T (+ A2[M,K] * W2[N,K]^T) (+bias)
// 128x128 block, BK=16, 256 threads = 8 warps (2x4), warp tile 64x32.
#define BMg 128
#define BNg 128
#define BKg 16
#define PADg 20

__global__ __launch_bounds__(256) void gemm_tf32_kernel(
    const float* __restrict__ A, const float* __restrict__ W,
    const float* __restrict__ A2, const float* __restrict__ W2,
    float* __restrict__ C, int N, int K, const float* __restrict__ bias)
{
    __shared__ uint32_t As[2][BMg * PADg];
    __shared__ uint32_t Bs[2][BNg * PADg];

    const int tid = threadIdx.x;
    const int lane = tid & 31;
    const int warp = tid >> 5;
    const int wm = warp >> 2;
    const int wn = warp & 3;
    const int bm = blockIdx.y * BMg;
    const int bn = blockIdx.x * BNg;
    const int mBase = wm * 64;
    const int nBase = wn * 32;

    // staging chunk coords: chunk0 = tid, chunk1 = tid + 256
    const int r0 = tid >> 2;
    const int cf0 = (tid & 3) << 2;
    const int r1 = r0 + 64;

    float acc[4][4][4];
#pragma unroll
    for (int mi = 0; mi < 4; mi++)
#pragma unroll
        for (int ni = 0; ni < 4; ni++)
#pragma unroll
            for (int e = 0; e < 4; e++) acc[mi][ni][e] = 0.f;

    const int nk = K / BKg;
    const int nkt = A2 ? (2 * nk) : nk;

    // prefetch kt = 0
    float4 ra0 = *(const float4*)(A + (size_t)(bm + r0) * K + cf0);
    float4 ra1 = *(const float4*)(A + (size_t)(bm + r1) * K + cf0);
    float4 rb0 = *(const float4*)(W + (size_t)(bn + r0) * K + cf0);
    float4 rb1 = *(const float4*)(W + (size_t)(bn + r1) * K + cf0);

    const int row4 = lane >> 2;
    const int col4 = lane & 3;

    for (int kt = 0; kt < nkt; kt++) {
        int buf = kt & 1;
        sts_cvt(&As[buf][r0 * PADg + cf0], ra0);
        sts_cvt(&As[buf][r1 * PADg + cf0], ra1);
        sts_cvt(&Bs[buf][r0 * PADg + cf0], rb0);
        sts_cvt(&Bs[buf][r1 * PADg + cf0], rb1);
        __syncthreads();

        if (kt + 1 < nkt) {
            int k2 = kt + 1;
            const float* Ap; const float* Wp; int ko;
            if (k2 < nk) { Ap = A;  Wp = W;  ko = k2 * BKg; }
            else         { Ap = A2; Wp = W2; ko = (k2 - nk) * BKg; }
            ra0 = *(const float4*)(Ap + (size_t)(bm + r0) * K + ko + cf0);
            ra1 = *(const float4*)(Ap + (size_t)(bm + r1) * K + ko + cf0);
            rb0 = *(const float4*)(Wp + (size_t)(bn + r0) * K + ko + cf0);
            rb1 = *(const float4*)(Wp + (size_t)(bn + r1) * K + ko + cf0);
        }

        const uint32_t* as = As[buf];
        const uint32_t* bs = Bs[buf];
#pragma unroll
        for (int kk = 0; kk < BKg; kk += 8) {
            uint32_t af[4][4], bf[4][2];
#pragma unroll
            for (int mi = 0; mi < 4; mi++) {
                int m0 = mBase + mi * 16;
                af[mi][0] = as[(m0 + row4) * PADg + kk + col4];
                af[mi][1] = as[(m0 + row4 + 8) * PADg + kk + col4];
                af[mi][2] = as[(m0 + row4) * PADg + kk + col4 + 4];
                af[mi][3] = as[(m0 + row4 + 8) * PADg + kk + col4 + 4];
            }
#pragma unroll
            for (int ni = 0; ni < 4; ni++) {
                int n0 = nBase + ni * 8;
                bf[ni][0] = bs[(n0 + row4) * PADg + kk + col4];
                bf[ni][1] = bs[(n0 + row4) * PADg + kk + col4 + 4];
            }
#pragma unroll
            for (int mi = 0; mi < 4; mi++)
#pragma unroll
                for (int ni = 0; ni < 4; ni++)
                    mma_tf32(acc[mi][ni], af[mi], bf[ni]);
        }
        // one barrier per k-tile is sufficient: STS(kt+1) targets buf^1, which
        // was last read in compute(kt-1), fully ordered by the barrier above.
    }

#pragma unroll
    for (int mi = 0; mi < 4; mi++) {
        int r = bm + mBase + mi * 16 + row4;
#pragma unroll
        for (int ni = 0; ni < 4; ni++) {
            int cb = bn + nBase + ni * 8 + 2 * col4;
            float2 b2 = make_float2(0.f, 0.f);
            if (bias) { b2.x = bias[cb]; b2.y = bias[cb + 1]; }
            float2 v0 = make_float2(acc[mi][ni][0] + b2.x, acc[mi][ni][1] + b2.y);
            float2 v1 = make_float2(acc[mi][ni][2] + b2.x, acc[mi][ni][3] + b2.y);
            *(float2*)(C + (size_t)r * N + cb) = v0;
            *(float2*)(C + (size_t)(r + 8) * N + cb) = v1;
        }
    }
}

// ---------------- residual add + RMSNorm ----------------
__global__ __launch_bounds__(256) void rmsnorm_kernel(
    float* __restrict__ y2, const float* __restrict__ x, const float* __restrict__ w)
{
    int m = blockIdx.x;
    float* yrow = y2 + (size_t)m * Hh;
    const float* xrow = x + (size_t)m * Hh;

    float ss = 0.f;
    for (int i = threadIdx.x; i < Hh; i += 256) {
        float t = yrow[i] + xrow[i];
        ss += t * t;
    }
#pragma unroll
    for (int off = 16; off > 0; off >>= 1)
        ss += __shfl_xor_sync(0xffffffffu, ss, off);

    __shared__ float red[9];
    int lane = threadIdx.x & 31, wid = threadIdx.x >> 5;
    if (lane == 0) red[wid] = ss;
    __syncthreads();
    if (threadIdx.x == 0) {
        float tot = 0.f;
        for (int i = 0; i < 8; i++) tot += red[i];
        red[8] = rsqrtf(tot / (float)Hh + EPSc);
    }
    __syncthreads();
    float inv = red[8];
    for (int i = threadIdx.x; i < Hh; i += 256) {
        float t = yrow[i] + xrow[i];
        yrow[i] = t * w[i] * inv;
    }
}

// ---------------- RoPE in place on qk buffer ----------------
__global__ __launch_bounds__(128) void rope_kernel(
    float* __restrict__ qkbuf, const float* __restrict__ freqs,
    const int* __restrict__ positions)
{
    int mh = blockIdx.x;
    int m = mh / NHh, h = mh % NHh;
    int pos = positions[m];
    int t = threadIdx.x;
    int isK = t >> 6;
    int d = t & 63;

    size_t base = (size_t)m * QKW + (size_t)h * 256 + (size_t)isK * 128;
    float f1 = freqs[(size_t)pos * HDd + d];
    float f2 = freqs[(size_t)pos * HDd + d + 64];
    float c1 = cosf(f1), s1 = sinf(f1);
    float c2 = cosf(f2), s2 = sinf(f2);
    float x1 = qkbuf[base + d];
    float x2 = qkbuf[base + d + 64];
    qkbuf[base + d]      = x1 * c1 - x2 * s1;
    qkbuf[base + d + 64] = x2 * c2 + x1 * s2;
}

// ---------------- tensor-core causal flash attention ----------------
// TQ=128 (8 warps x 16 rows), TK=32. QK^T via 3xTF32 (hi/lo split of Q and K,
// residual error ~1e-6 so logits keep fp32 accuracy). PV plain TF32.
// Fragment layouts identical to the (validated) gemm_tf32_kernel.
#define FTQ 128
#define FTK 32
#define FPD 132   // Q/K/V row pitch (u32): conflict-free frag reads, 16B aligned
#define FPP 36    // P row pitch

// dynamic smem (u32): Qhi | Qlo | Khi | Klo | Vs | Ps
#define FQ_SZ (FTQ * FPD)
#define FK_SZ (FTK * FPD)
#define FP_SZ (FTQ * FPP)
#define FSMEM_BYTES ((2 * FQ_SZ + 3 * FK_SZ + FP_SZ) * 4)

__global__ __launch_bounds__(256, 1) void flash_tc_kernel(
    const float* __restrict__ qkbuf, const float* __restrict__ vbuf,
    float* __restrict__ attn)
{
    extern __shared__ uint32_t fsm[];
    uint32_t* Qhi = fsm;
    uint32_t* Qlo = Qhi + FQ_SZ;
    uint32_t* Khi = Qlo + FQ_SZ;
    uint32_t* Klo = Khi + FK_SZ;
    uint32_t* Vs  = Klo + FK_SZ;   // natural [kv][d] layout; PV reads transposed
    uint32_t* Ps  = Vs  + FK_SZ;

    const int qt = gridDim.x - 1 - blockIdx.x;   // heavy tiles first
    const int h  = blockIdx.y;
    const int b  = blockIdx.z;
    const int q0 = qt * FTQ;
    const int tid  = threadIdx.x;
    const int lane = tid & 31;
    const int warp = tid >> 5;
    const int wm16 = warp * 16;
    const int row4 = lane >> 2;
    const int col4 = lane & 3;
    const int bS = b * Ss;
    const int hq = h * 256;
    const float scale = 0.08838834764831845f;   // 1/sqrt(128)

    // ---- stage Q (scaled, hi/lo split) ----
    for (int c = tid; c < FTQ * 32; c += 256) {
        int row = c >> 5, colf = (c & 31) << 2;
        float4 q4 = *(const float4*)(qkbuf + (size_t)(bS + q0 + row) * QKW + hq + colf);
        uint4 hi, lo; float x;
        x = q4.x * scale; hi.x = f2tf(x); lo.x = f2tf(x - __uint_as_float(hi.x));
        x = q4.y * scale; hi.y = f2tf(x); lo.y = f2tf(x - __uint_as_float(hi.y));
        x = q4.z * scale; hi.z = f2tf(x); lo.z = f2tf(x - __uint_as_float(hi.z));
        x = q4.w * scale; hi.w = f2tf(x); lo.w = f2tf(x - __uint_as_float(hi.w));
        *(uint4*)&Qhi[row * FPD + colf] = hi;
        *(uint4*)&Qlo[row * FPD + colf] = lo;
    }

    float O[16][4];
#pragma unroll
    for (int ni = 0; ni < 16; ni++)
#pragma unroll
        for (int e = 0; e < 4; e++) O[ni][e] = 0.f;
    float mrow0 = -1e30f, mrow1 = -1e30f, lrow0 = 0.f, lrow1 = 0.f;

    const int kend = q0 + FTQ;
    for (int j0 = 0; j0 < kend; j0 += FTK) {
        __syncthreads();   // prior compute done before overwriting K/V (also orders Q stage at j0=0)
        // ---- stage K (hi/lo) and V (plain tf32) ----
        for (int c = tid; c < FTK * 32; c += 256) {
            int row = c >> 5, colf = (c & 31) << 2;
            float4 k4 = *(const float4*)(qkbuf + (size_t)(bS + j0 + row) * QKW + hq + 128 + colf);
            uint4 hi, lo;
            hi.x = f2tf(k4.x); lo.x = f2tf(k4.x - __uint_as_float(hi.x));
            hi.y = f2tf(k4.y); lo.y = f2tf(k4.y - __uint_as_float(hi.y));
            hi.z = f2tf(k4.z); lo.z = f2tf(k4.z - __uint_as_float(hi.z));
            hi.w = f2tf(k4.w); lo.w = f2tf(k4.w - __uint_as_float(hi.w));
            *(uint4*)&Khi[row * FPD + colf] = hi;
            *(uint4*)&Klo[row * FPD + colf] = lo;
            float4 v4 = *(const float4*)(vbuf + (size_t)(bS + j0 + row) * Pp + h * HDd + colf);
            uint4 vv;
            vv.x = f2tf(v4.x); vv.y = f2tf(v4.y); vv.z = f2tf(v4.z); vv.w = f2tf(v4.w);
            *(uint4*)&Vs[row * FPD + colf] = vv;
        }
        __syncthreads();

        bool active = (j0 <= q0 + wm16 + 15);   // warp-uniform
        if (active) {
            // ---- S = Q K^T (3xTF32) ----
            float s[4][4];
#pragma unroll
            for (int ni = 0; ni < 4; ni++)
#pragma unroll
                for (int e = 0; e < 4; e++) s[ni][e] = 0.f;

#pragma unroll
            for (int kk = 0; kk < HDd; kk += 8) {
                int ra = (wm16 + row4) * FPD + kk + col4;
                int rb8 = ra + 8 * FPD;
                uint32_t ahi[4] = {Qhi[ra], Qhi[rb8], Qhi[ra + 4], Qhi[rb8 + 4]};
                uint32_t alo[4] = {Qlo[ra], Qlo[rb8], Qlo[ra + 4], Qlo[rb8 + 4]};
#pragma unroll
                for (int ni = 0; ni < 4; ni++) {
                    int rn = (ni * 8 + row4) * FPD + kk + col4;
                    uint32_t bh[2] = {Khi[rn], Khi[rn + 4]};
                    uint32_t bl[2] = {Klo[rn], Klo[rn + 4]};
                    mma_tf32(s[ni], ahi, bh);
                    mma_tf32(s[ni], alo, bh);
                    mma_tf32(s[ni], ahi, bl);
                }
            }

            // ---- causal mask ----
            if (j0 + FTK - 1 > q0 + wm16) {
                int qlo = q0 + wm16 + row4;
                int qhi = qlo + 8;
#pragma unroll
                for (int ni = 0; ni < 4; ni++) {
                    int kp = j0 + ni * 8 + 2 * col4;
                    if (kp     > qlo) s[ni][0] = -1e30f;
                    if (kp + 1 > qlo) s[ni][1] = -1e30f;
                    if (kp     > qhi) s[ni][2] = -1e30f;
                    if (kp + 1 > qhi) s[ni][3] = -1e30f;
                }
            }

            // ---- online softmax (rows row4 / row4+8; quad = lanes xor 1,2) ----
            float mx0 = -1e30f, mx1 = -1e30f;
#pragma unroll
            for (int ni = 0; ni < 4; ni++) {
                mx0 = fmaxf(mx0, fmaxf(s[ni][0], s[ni][1]));
                mx1 = fmaxf(mx1, fmaxf(s[ni][2], s[ni][3]));
            }
            mx0 = fmaxf(mx0, __shfl_xor_sync(0xffffffffu, mx0, 1));
            mx0 = fmaxf(mx0, __shfl_xor_sync(0xffffffffu, mx0, 2));
            mx1 = fmaxf(mx1, __shfl_xor_sync(0xffffffffu, mx1, 1));
            mx1 = fmaxf(mx1, __shfl_xor_sync(0xffffffffu, mx1, 2));
            float mn0 = fmaxf(mrow0, mx0), mn1 = fmaxf(mrow1, mx1);
            float al0 = __expf(mrow0 - mn0), al1 = __expf(mrow1 - mn1);
            mrow0 = mn0; mrow1 = mn1;

            float sum0 = 0.f, sum1 = 0.f;
            int pbase = (wm16 + row4) * FPP + 2 * col4;
#pragma unroll
            for (int ni = 0; ni < 4; ni++) {
                float p0 = __expf(s[ni][0] - mn0);
                float p1 = __expf(s[ni][1] - mn0);
                float p2 = __expf(s[ni][2] - mn1);
                float p3 = __expf(s[ni][3] - mn1);
                sum0 += p0 + p1; sum1 += p2 + p3;
                Ps[pbase + ni * 8]                 = f2tf(p0);
                Ps[pbase + ni * 8 + 1]             = f2tf(p1);
                Ps[pbase + ni * 8 + 8 * FPP]       = f2tf(p2);
                Ps[pbase + ni * 8 + 8 * FPP + 1]   = f2tf(p3);
            }
            lrow0 = lrow0 * al0 + sum0;
            lrow1 = lrow1 * al1 + sum1;
#pragma unroll
            for (int ni = 0; ni < 16; ni++) {
                O[ni][0] *= al0; O[ni][1] *= al0;
                O[ni][2] *= al1; O[ni][3] *= al1;
            }
            __syncwarp();   // Ps rows are warp-private: warp-level sync suffices

            // ---- O += P V ----
#pragma unroll
            for (int kp = 0; kp < FTK; kp += 8) {
                int pa = (wm16 + row4) * FPP + kp + col4;
                uint32_t a[4] = {Ps[pa], Ps[pa + 8 * FPP], Ps[pa + 4], Ps[pa + 8 * FPP + 4]};
#pragma unroll
                for (int ni = 0; ni < 16; ni++) {
                    int vb = (kp + col4) * FPD + ni * 8 + row4;   // B[n=d][k=kv] = Vs[kv][d]
                    uint32_t bv[2] = {Vs[vb], Vs[vb + 4 * FPD]};
                    mma_tf32(O[ni], a, bv);
                }
            }
        }
    }

    // ---- finalize ----
    lrow0 += __shfl_xor_sync(0xffffffffu, lrow0, 1);
    lrow0 += __shfl_xor_sync(0xffffffffu, lrow0, 2);
    lrow1 += __shfl_xor_sync(0xffffffffu, lrow1, 1);
    lrow1 += __shfl_xor_sync(0xffffffffu, lrow1, 2);
    float inv0 = 1.f / lrow0, inv1 = 1.f / lrow1;

    size_t ob0 = (size_t)(bS + q0 + wm16 + row4) * Pp + h * HDd;
    size_t ob1 = ob0 + (size_t)8 * Pp;
#pragma unroll
    for (int ni = 0; ni < 16; ni++) {
        int cb = ni * 8 + 2 * col4;
        *(float2*)(attn + ob0 + cb) = make_float2(O[ni][0] * inv0, O[ni][1] * inv0);
        *(float2*)(attn + ob1 + cb) = make_float2(O[ni][2] * inv1, O[ni][3] * inv1);
    }
}

// ---------------- tail outputs ----------------
__global__ void tails_kernel(const float* __restrict__ hs, const float* __restrict__ y1,
                             float* __restrict__ out)
{
    int i = blockIdx.x * 256 + threadIdx.x;
    size_t off1 = (size_t)Mm * Hh;
    size_t off2 = off1 + (size_t)Bb * Hh;
    if (i < Bb * Hh) {
        int b = i / Hh, hh = i % Hh;
        out[off1 + i] = hs[((size_t)b * Ss + (Ss - 1)) * Hh + hh];
    }
    if (i < Bb * H2) {
        int b = i / H2, oo = i % H2;
        out[off2 + i] = y1[((size_t)b * Ss + (Ss - 1)) * H2 + oo];
    }
}

// ---------------- launch ----------------
extern "C" void kernel_launch(void* const* d_in, const int* in_sizes, int n_in,
                              void* d_out, int out_size)
{
    (void)in_sizes; (void)n_in; (void)out_size;
    const float* hs      = (const float*)d_in[0];
    const float* freqs   = (const float*)d_in[1];
    const int*   pos     = (const int*)  d_in[2];
    const float* Wqk     = (const float*)d_in[3];
    const float* Wv      = (const float*)d_in[4];
    const float* Wo      = (const float*)d_in[5];
    const float* conv1_w = (const float*)d_in[6];
    const float* conv1_b = (const float*)d_in[7];
    const float* conv2_w = (const float*)d_in[8];
    const float* conv2_b = (const float*)d_in[9];
    const float* ln_w    = (const float*)d_in[10];
    const float* lf1c    = (const float*)d_in[11];
    const float* lf2c    = (const float*)d_in[12];
    float* out = (float*)d_out;

    float *v, *xprev, *y1, *y1prev, *lfout, *qk, *attn;
    float *w1a, *w1b, *w2a, *w2b;
    cudaGetSymbolAddress((void**)&v,      g_v);
    cudaGetSymbolAddress((void**)&xprev,  g_xprev);
    cudaGetSymbolAddress((void**)&y1,     g_y1);
    cudaGetSymbolAddress((void**)&y1prev, g_y1prev);
    cudaGetSymbolAddress((void**)&lfout,  g_lfout);
    cudaGetSymbolAddress((void**)&qk,     g_qk);
    cudaGetSymbolAddress((void**)&attn,   g_attn);
    cudaGetSymbolAddress((void**)&w1a,    g_w1a);
    cudaGetSymbolAddress((void**)&w1b,    g_w1b);
    cudaGetSymbolAddress((void**)&w2a,    g_w2a);
    cudaGetSymbolAddress((void**)&w2b,    g_w2b);

    static bool attr_done = false;
    if (!attr_done) {
        cudaFuncSetAttribute(flash_tc_kernel,
                             cudaFuncAttributeMaxDynamicSharedMemorySize, FSMEM_BYTES);
        attr_done = true;
    }

    // 1) deinterleave conv weights
    {
        int n1 = H2 * Hh;
        deint_kernel<<<(n1 + 255) / 256, 256>>>(conv1_w, w1a, w1b, n1);
        int n2 = Hh * H2;
        deint_kernel<<<(n2 + 255) / 256, 256>>>(conv2_w, w2a, w2b, n2);
    }

    // 2) shifted hidden
    shift_kernel<<<Mm, 256>>>(hs, lf1c, xprev, Hh);

    // 3) v = hs @ Wv^T
    gemm_tf32_kernel<<<dim3(Pp / BNg, Mm / BMg), 256>>>(hs, Wv, nullptr, nullptr, v, Pp, Hh, nullptr);

    // 4) y1 = xprev @ w1a^T + hs @ w1b^T + b1   (fused dual-K)
    gemm_tf32_kernel<<<dim3(H2 / BNg, Mm / BMg), 256>>>(xprev, w1a, hs, w1b, y1, H2, Hh, conv1_b);

    // 5) shifted y1
    shift_kernel<<<Mm, 256>>>(y1, lf2c, y1prev, H2);

    // 6) y2 = y1prev @ w2a^T + y1 @ w2b^T + b2  (fused dual-K)
    gemm_tf32_kernel<<<dim3(Hh / BNg, Mm / BMg), 256>>>(y1prev, w2a, y1, w2b, lfout, Hh, H2, conv2_b);

    // 7) lf_out = rmsnorm(y2 + hs) * ln_w
    rmsnorm_kernel<<<Mm, 256>>>(lfout, hs, ln_w);

    // 8) qk = lf_out @ Wqk^T
    gemm_tf32_kernel<<<dim3(QKW / BNg, Mm / BMg), 256>>>(lfout, Wqk, nullptr, nullptr, qk, QKW, Hh, nullptr);

    // 9) RoPE in place
    rope_kernel<<<Mm * NHh, 128>>>(qk, freqs, pos);

    // 10) tensor-core causal flash attention
    flash_tc_kernel<<<dim3(Ss / FTQ, NHh, Bb), 256, FSMEM_BYTES>>>(qk, v, attn);

    // 11) output = attn @ Wo^T
    gemm_tf32_kernel<<<dim3(Hh / BNg, Mm / BMg), 256>>>(attn, Wo, nullptr, nullptr, out, Hh, Pp, nullptr);

    // 12) tails
    tails_kernel<<<(Bb * Hh + 255) / 256, 256>>>(hs, y1, out);
}